// round 7
// baseline (speedup 1.0000x reference)
#include <cuda_runtime.h>
#include <math.h>
#include <stdint.h>

#define Bb 2
#define Ss 2048
#define Dd 4096
#define Hh 32
#define HDh 128
#define HALFh 64
#define ALa 10
#define Mtok (Bb*Ss)

// ---- tf32 mma.sync GEMM config ----
#define BM 128
#define BN 128
#define BK 32
#define STAGE_FLOATS (BM*36)
#define STAGE_BYTES (2*STAGE_FLOATS*4)
#define NSTAGE 4
#define GEMM_SMEM (NSTAGE*STAGE_BYTES)

// ---- flash mma config ----
#define FQ 128
#define FKV 64
#define QSTR 132
#define KSTR 132
#define VSTR 68
#define PSTR2 68
#define SQ0 0
#define SK0 (128*QSTR)
#define SV0 (SK0 + 64*KSTR)
#define SP0 (SV0 + 128*VSTR)
#define FLASH_SMEM ((SP0 + 128*PSTR2)*4)

#define KSPL 8

// ---------------- scratch ----------------
__device__ float g_q[Bb*Ss*Dd];
__device__ float g_k[Bb*Ss*Dd];
__device__ float g_v[Bb*Ss*Dd];
__device__ float g_attn[Bb*Ss*Dd];
__device__ float g_ak[Bb*ALa*Dd];
__device__ float g_av[Bb*ALa*Dd];
__device__ float g_pk[KSPL*Bb*ALa*Dd];
__device__ float g_pv[KSPL*Bb*ALa*Dd];

__device__ __forceinline__ uint32_t s2u(const void* p){
    uint32_t r;
    asm("{ .reg .u64 t; cvta.to.shared.u64 t, %1; cvt.u32.u64 %0, t; }" : "=r"(r) : "l"(p));
    return r;
}

__device__ __forceinline__ void ldsm_x4(uint32_t* r, uint32_t addr){
    asm volatile("ldmatrix.sync.aligned.m8n8.x4.shared.b16 {%0,%1,%2,%3}, [%4];"
                 : "=r"(r[0]), "=r"(r[1]), "=r"(r[2]), "=r"(r[3]) : "r"(addr));
}

__device__ __forceinline__ uint32_t f2tf(uint32_t x){
    uint32_t y;
    asm("cvt.rna.tf32.f32 %0, %1;" : "=r"(y) : "r"(x));
    return y;
}

// split fp32 -> tf32 hi + tf32 lo (3xTF32 compensation)
__device__ __forceinline__ void split_tf32(uint32_t raw, uint32_t& hi, uint32_t& lo){
    float v = __uint_as_float(raw);
    uint32_t h = f2tf(raw);
    hi = h;
    float rem = v - __uint_as_float(h);
    lo = f2tf(__float_as_uint(rem));
}

__device__ __forceinline__ void mma_tf32(float* d, const uint32_t* a, const uint32_t* b){
    asm volatile(
        "mma.sync.aligned.m16n8k8.row.col.f32.tf32.tf32.f32 "
        "{%0,%1,%2,%3}, {%4,%5,%6,%7}, {%8,%9}, {%0,%1,%2,%3};"
        : "+f"(d[0]), "+f"(d[1]), "+f"(d[2]), "+f"(d[3])
        : "r"(a[0]), "r"(a[1]), "r"(a[2]), "r"(a[3]), "r"(b[0]), "r"(b[1]));
}

// ---------------- 3xTF32 mma.sync NT GEMM ----------------
__global__ __launch_bounds__(256) void gemm_mma(
    const float* __restrict__ A, const float* __restrict__ Bw,
    float* __restrict__ C, int M, int N, int K)
{
    extern __shared__ float sm_g[];
    const uint32_t sbase = s2u(sm_g);
    const int t = threadIdx.x;
    const int m0 = blockIdx.y * BM;
    const int n0 = blockIdx.x * BN;
    const int NCH = K / BK;

    const int lane = t & 31;
    const int wid  = t >> 5;
    const int wm   = wid & 3;
    const int wn   = wid >> 2;
    const int ldr = t >> 3;
    const int ldq = t & 7;

    float d[2][8][4];
    #pragma unroll
    for (int mt = 0; mt < 2; mt++)
        #pragma unroll
        for (int nt = 0; nt < 8; nt++)
            #pragma unroll
            for (int c = 0; c < 4; c++) d[mt][nt][c] = 0.f;

    const uint32_t aOff = (uint32_t)(wm*32 + (lane & 15)) * 144u + ((lane >> 4) << 4);
    const uint32_t bOff = (uint32_t)(wn*64 + ((lane >> 4) << 3) + (lane & 7)) * 144u
                          + (((lane >> 3) & 1) << 4);

    auto prefetch = [&](int chunk, int stage){
        const int k0 = chunk * BK;
        const uint32_t sA = sbase + (uint32_t)stage * STAGE_BYTES;
        const uint32_t sB = sA + STAGE_FLOATS*4;
        #pragma unroll
        for (int i = 0; i < 4; i++) {
            int row = ldr + i*32;
            int ar = m0 + row; if (ar > M-1) ar = M-1;
            const float* ga = A  + (size_t)ar * K + k0 + ldq*4;
            const float* gb = Bw + (size_t)(n0 + row) * K + k0 + ldq*4;
            uint32_t so = (uint32_t)row * 144u + (uint32_t)ldq * 16u;
            asm volatile("cp.async.cg.shared.global [%0], [%1], 16;" :: "r"(sA + so), "l"(ga));
            asm volatile("cp.async.cg.shared.global [%0], [%1], 16;" :: "r"(sB + so), "l"(gb));
        }
        asm volatile("cp.async.commit_group;" ::: "memory");
    };

    #pragma unroll
    for (int p = 0; p < NSTAGE; p++) prefetch(p, p);

    for (int n = 0; n < NCH; n++) {
        const int s = n & (NSTAGE - 1);
        asm volatile("cp.async.wait_group %0;" :: "n"(NSTAGE-1) : "memory");
        __syncthreads();

        const uint32_t sA = sbase + (uint32_t)s * STAGE_BYTES;
        const uint32_t sB = sA + STAGE_FLOATS*4;

        #pragma unroll
        for (int ks = 0; ks < 4; ks++) {
            const uint32_t kb = (uint32_t)ks * 32u;
            uint32_t ah[2][4], al[2][4], bh[8][2], bl[8][2];
            #pragma unroll
            for (int mt = 0; mt < 2; mt++) {
                uint32_t r4[4];
                ldsm_x4(r4, sA + aOff + (uint32_t)mt*(16u*144u) + kb);
                #pragma unroll
                for (int c = 0; c < 4; c++) split_tf32(r4[c], ah[mt][c], al[mt][c]);
            }
            #pragma unroll
            for (int ntp = 0; ntp < 4; ntp++) {
                uint32_t r4[4];
                ldsm_x4(r4, sB + bOff + (uint32_t)ntp*(16u*144u) + kb);
                split_tf32(r4[0], bh[2*ntp][0],   bl[2*ntp][0]);
                split_tf32(r4[1], bh[2*ntp][1],   bl[2*ntp][1]);
                split_tf32(r4[2], bh[2*ntp+1][0], bl[2*ntp+1][0]);
                split_tf32(r4[3], bh[2*ntp+1][1], bl[2*ntp+1][1]);
            }
            #pragma unroll
            for (int mt = 0; mt < 2; mt++)
                #pragma unroll
                for (int nt = 0; nt < 8; nt++) {
                    mma_tf32(d[mt][nt], ah[mt], bh[nt]);
                    mma_tf32(d[mt][nt], ah[mt], bl[nt]);
                    mma_tf32(d[mt][nt], al[mt], bh[nt]);
                }
        }
        __syncthreads();

        int pn = n + NSTAGE; if (pn >= NCH) pn = 0;
        prefetch(pn, s);
    }

    const int g  = lane >> 2;
    const int tq = lane & 3;
    #pragma unroll
    for (int mt = 0; mt < 2; mt++) {
        int row = m0 + wm*32 + mt*16 + g;
        #pragma unroll
        for (int nt = 0; nt < 8; nt++) {
            int col = n0 + wn*64 + nt*8 + 2*tq;
            if (row < M)
                *(float2*)&C[(size_t)row * N + col] = make_float2(d[mt][nt][0], d[mt][nt][1]);
            if (row + 8 < M)
                *(float2*)&C[(size_t)(row+8) * N + col] = make_float2(d[mt][nt][2], d[mt][nt][3]);
        }
    }
}

// ---------------- skinny adapter GEMM (M=20, fp32, split-K partials) ----------------
__global__ __launch_bounds__(128) void gemm_skinny(
    const float* __restrict__ Aad, const float* __restrict__ wk, const float* __restrict__ wv)
{
    __shared__ float As[20][33];
    __shared__ float Bs[128][33];
    const int t = threadIdx.x;
    const int n0 = blockIdx.x * 128;
    const int kz = blockIdx.y;
    const float* W = blockIdx.z ? wv : wk;
    float* P = (blockIdx.z ? g_pv : g_pk) + (size_t)kz * (20*4096);

    float acc[20];
    #pragma unroll
    for (int m = 0; m < 20; m++) acc[m] = 0.f;

    for (int k0 = kz*512; k0 < kz*512 + 512; k0 += 32) {
        for (int i = t; i < 640; i += 128) {
            int r = i >> 5, c = i & 31;
            As[r][c] = Aad[(size_t)r*4096 + k0 + c];
        }
        #pragma unroll
        for (int i = 0; i < 8; i++) {
            int idx = t + i*128;
            int r = idx >> 3, cq = idx & 7;
            float4 v = *(const float4*)&W[(size_t)(n0 + r)*4096 + k0 + cq*4];
            Bs[r][cq*4+0] = v.x; Bs[r][cq*4+1] = v.y;
            Bs[r][cq*4+2] = v.z; Bs[r][cq*4+3] = v.w;
        }
        __syncthreads();
        #pragma unroll
        for (int k = 0; k < 32; k++) {
            float bv = Bs[t][k];
            #pragma unroll
            for (int m = 0; m < 20; m++) acc[m] += As[m][k] * bv;
        }
        __syncthreads();
    }
    #pragma unroll
    for (int m = 0; m < 20; m++) P[(size_t)m*4096 + n0 + t] = acc[m];
}

__global__ void skinny_reduce()
{
    int i = blockIdx.x*256 + threadIdx.x;
    if (i >= 20*4096) return;
    float sk = 0.f, sv = 0.f;
    #pragma unroll
    for (int z = 0; z < KSPL; z++) {
        sk += g_pk[(size_t)z*(20*4096) + i];
        sv += g_pv[(size_t)z*(20*4096) + i];
    }
    g_ak[i] = sk;
    g_av[i] = sv;
}

// ---------------- RoPE ----------------
__global__ void rope_kernel(float* __restrict__ T,
                            const float* __restrict__ cosT,
                            const float* __restrict__ sinT)
{
    int idx = blockIdx.x * blockDim.x + threadIdx.x;
    if (idx >= Bb*Ss*Hh*HALFh) return;
    int p = idx & (HALFh - 1);
    int s = (idx >> 11) & (Ss - 1);
    float c  = cosT[s*HALFh + p];
    float sn = sinT[s*HALFh + p];
    float2 v = *(float2*)&T[2*(size_t)idx];
    float2 r;
    r.x = v.x * c - v.y * sn;
    r.y = v.x * sn + v.y * c;
    *(float2*)&T[2*(size_t)idx] = r;
}

// ---------------- flash attention via 3xTF32 mma.sync ----------------
// grid (S/FQ, B*H), 256 threads, 8 warps * 16 q-rows each.
__global__ __launch_bounds__(256, 1) void flash_mma()
{
    extern __shared__ float fs[];
    const uint32_t sb = s2u(fs);
    const int t = threadIdx.x, lane = t & 31, w = t >> 5;
    const int bh = blockIdx.y, b = bh >> 5, h = bh & 31;
    const int q0 = (int)(gridDim.x - 1 - blockIdx.x) * FQ;   // big tiles first
    const size_t headbase = (size_t)b * Ss * Dd + (size_t)h * HDh;
    const int g = lane >> 2, tq = lane & 3;
    const float rscale = 0.08838834764831844f;
    const float NEGINF = __int_as_float(0xff800000);

    // load Q (128x128) into smem (stride QSTR)
    {
        const float* Qg = g_q + headbase + (size_t)q0 * Dd;
        #pragma unroll
        for (int i = 0; i < 16; i++) {
            int idx = t + i*256;
            int r = idx >> 5, cq = idx & 31;
            uint32_t dst = sb + (uint32_t)((SQ0 + r*QSTR + cq*4)*4);
            asm volatile("cp.async.cg.shared.global [%0], [%1], 16;"
                         :: "r"(dst), "l"(Qg + (size_t)r*Dd + cq*4));
        }
        asm volatile("cp.async.commit_group;" ::: "memory");
    }

    const uint32_t aQ = sb + (uint32_t)((SQ0 + (w*16 + (lane&15))*QSTR)*4) + ((lane>>4)<<4);
    const uint32_t bK = sb + (uint32_t)((SK0 + (((lane>>4)<<3) + (lane&7))*KSTR)*4) + (((lane>>3)&1)<<4);
    const uint32_t aP = sb + (uint32_t)((SP0 + (w*16 + (lane&15))*PSTR2)*4) + ((lane>>4)<<4);
    const uint32_t bV = sb + (uint32_t)((SV0 + (((lane>>4)<<3) + (lane&7))*VSTR)*4) + (((lane>>3)&1)<<4);

    float o[16][4];
    #pragma unroll
    for (int nt = 0; nt < 16; nt++) { o[nt][0]=o[nt][1]=o[nt][2]=o[nt][3]=0.f; }
    float m0r = -1e30f, m1r = -1e30f, l0r = 0.f, l1r = 0.f;

    const int ig0 = q0 + w*16 + g;
    const int ig1 = ig0 + 8;

    for (int j0 = 0; j0 < q0 + FQ; j0 += FKV) {
        __syncthreads();   // previous block fully consumed
        const float* Kg = g_k + headbase + (size_t)j0 * Dd;
        const float* Vg = g_v + headbase + (size_t)j0 * Dd;
        #pragma unroll
        for (int i = 0; i < 8; i++) {
            int idx = t + i*256;
            int r = idx >> 5, cq = idx & 31;
            uint32_t dst = sb + (uint32_t)((SK0 + r*KSTR + cq*4)*4);
            asm volatile("cp.async.cg.shared.global [%0], [%1], 16;"
                         :: "r"(dst), "l"(Kg + (size_t)r*Dd + cq*4));
        }
        asm volatile("cp.async.commit_group;" ::: "memory");
        // V transposed into Vt[d][key]
        #pragma unroll
        for (int i = 0; i < 8; i++) {
            int idx = t + i*256;
            int r = idx >> 5, cq = idx & 31;
            float4 v = *(const float4*)(Vg + (size_t)r*Dd + cq*4);
            fs[SV0 + (cq*4+0)*VSTR + r] = v.x;
            fs[SV0 + (cq*4+1)*VSTR + r] = v.y;
            fs[SV0 + (cq*4+2)*VSTR + r] = v.z;
            fs[SV0 + (cq*4+3)*VSTR + r] = v.w;
        }
        asm volatile("cp.async.wait_group 0;" ::: "memory");
        __syncthreads();

        // ---- S = Q @ K^T (3xTF32) ----
        float s[8][4];
        #pragma unroll
        for (int nt = 0; nt < 8; nt++) { s[nt][0]=s[nt][1]=s[nt][2]=s[nt][3]=0.f; }
        #pragma unroll
        for (int ks = 0; ks < 16; ks++) {
            uint32_t qr[4], qh[4], ql[4];
            ldsm_x4(qr, aQ + ks*32);
            #pragma unroll
            for (int c = 0; c < 4; c++) split_tf32(qr[c], qh[c], ql[c]);
            #pragma unroll
            for (int ntp = 0; ntp < 4; ntp++) {
                uint32_t r4[4];
                ldsm_x4(r4, bK + (uint32_t)ntp*(16u*KSTR*4u) + ks*32);
                uint32_t b0h[2], b0l[2], b1h[2], b1l[2];
                split_tf32(r4[0], b0h[0], b0l[0]);
                split_tf32(r4[1], b0h[1], b0l[1]);
                split_tf32(r4[2], b1h[0], b1l[0]);
                split_tf32(r4[3], b1h[1], b1l[1]);
                mma_tf32(s[2*ntp],   qh, b0h);
                mma_tf32(s[2*ntp],   qh, b0l);
                mma_tf32(s[2*ntp],   ql, b0h);
                mma_tf32(s[2*ntp+1], qh, b1h);
                mma_tf32(s[2*ntp+1], qh, b1l);
                mma_tf32(s[2*ntp+1], ql, b1h);
            }
        }

        // ---- mask + online softmax ----
        float mx0 = -1e30f, mx1 = -1e30f;
        #pragma unroll
        for (int nt = 0; nt < 8; nt++) {
            int jg = j0 + nt*8 + 2*tq;
            s[nt][0] = (jg   > ig0) ? NEGINF : s[nt][0]*rscale;
            s[nt][1] = (jg+1 > ig0) ? NEGINF : s[nt][1]*rscale;
            s[nt][2] = (jg   > ig1) ? NEGINF : s[nt][2]*rscale;
            s[nt][3] = (jg+1 > ig1) ? NEGINF : s[nt][3]*rscale;
            mx0 = fmaxf(mx0, fmaxf(s[nt][0], s[nt][1]));
            mx1 = fmaxf(mx1, fmaxf(s[nt][2], s[nt][3]));
        }
        mx0 = fmaxf(mx0, __shfl_xor_sync(0xffffffffu, mx0, 1));
        mx0 = fmaxf(mx0, __shfl_xor_sync(0xffffffffu, mx0, 2));
        mx1 = fmaxf(mx1, __shfl_xor_sync(0xffffffffu, mx1, 1));
        mx1 = fmaxf(mx1, __shfl_xor_sync(0xffffffffu, mx1, 2));
        float mn0 = fmaxf(m0r, mx0), mn1 = fmaxf(m1r, mx1);
        float co0 = __expf(m0r - mn0), co1 = __expf(m1r - mn1);
        float sum0 = 0.f, sum1 = 0.f;
        #pragma unroll
        for (int nt = 0; nt < 8; nt++) {
            s[nt][0] = __expf(s[nt][0] - mn0);
            s[nt][1] = __expf(s[nt][1] - mn0);
            s[nt][2] = __expf(s[nt][2] - mn1);
            s[nt][3] = __expf(s[nt][3] - mn1);
            sum0 += s[nt][0] + s[nt][1];
            sum1 += s[nt][2] + s[nt][3];
        }
        sum0 += __shfl_xor_sync(0xffffffffu, sum0, 1);
        sum0 += __shfl_xor_sync(0xffffffffu, sum0, 2);
        sum1 += __shfl_xor_sync(0xffffffffu, sum1, 1);
        sum1 += __shfl_xor_sync(0xffffffffu, sum1, 2);
        l0r = l0r * co0 + sum0;  m0r = mn0;
        l1r = l1r * co1 + sum1;  m1r = mn1;

        // P -> smem (warp-private 16 rows)
        #pragma unroll
        for (int nt = 0; nt < 8; nt++) {
            *(float2*)&fs[SP0 + (w*16 + g)*PSTR2   + nt*8 + 2*tq] = make_float2(s[nt][0], s[nt][1]);
            *(float2*)&fs[SP0 + (w*16 + g+8)*PSTR2 + nt*8 + 2*tq] = make_float2(s[nt][2], s[nt][3]);
        }
        __syncwarp();

        // rescale O
        #pragma unroll
        for (int nt = 0; nt < 16; nt++) {
            o[nt][0] *= co0; o[nt][1] *= co0;
            o[nt][2] *= co1; o[nt][3] *= co1;
        }

        // ---- O += P @ V (3xTF32) ----
        #pragma unroll
        for (int ks = 0; ks < 8; ks++) {
            uint32_t pr[4], ph[4], pl[4];
            ldsm_x4(pr, aP + ks*32);
            #pragma unroll
            for (int c = 0; c < 4; c++) split_tf32(pr[c], ph[c], pl[c]);
            #pragma unroll
            for (int ntp = 0; ntp < 8; ntp++) {
                uint32_t r4[4];
                ldsm_x4(r4, bV + (uint32_t)ntp*(16u*VSTR*4u) + ks*32);
                uint32_t b0h[2], b0l[2], b1h[2], b1l[2];
                split_tf32(r4[0], b0h[0], b0l[0]);
                split_tf32(r4[1], b0h[1], b0l[1]);
                split_tf32(r4[2], b1h[0], b1l[0]);
                split_tf32(r4[3], b1h[1], b1l[1]);
                mma_tf32(o[2*ntp],   ph, b0h);
                mma_tf32(o[2*ntp],   ph, b0l);
                mma_tf32(o[2*ntp],   pl, b0h);
                mma_tf32(o[2*ntp+1], ph, b1h);
                mma_tf32(o[2*ntp+1], ph, b1l);
                mma_tf32(o[2*ntp+1], pl, b1h);
            }
        }
    }

    // epilogue
    float inv0 = 1.f / l0r, inv1 = 1.f / l1r;
    float* Og = g_attn + headbase + (size_t)(q0 + w*16) * Dd;
    #pragma unroll
    for (int nt = 0; nt < 16; nt++) {
        *(float2*)&Og[(size_t)g*Dd     + nt*8 + 2*tq] = make_float2(o[nt][0]*inv0, o[nt][1]*inv0);
        *(float2*)&Og[(size_t)(g+8)*Dd + nt*8 + 2*tq] = make_float2(o[nt][2]*inv1, o[nt][3]*inv1);
    }
}

// ---------------- adapter attention ----------------
__global__ __launch_bounds__(128) void adapter_kernel(const float* __restrict__ gate)
{
    __shared__ __align__(16) float ak[ALa][HDh];
    __shared__ __align__(16) float av[ALa][HDh];
    const int t = threadIdx.x;
    const int bh = blockIdx.y;
    const int b = bh >> 5, h = bh & 31;
    const int s0 = blockIdx.x * 4;

    #pragma unroll
    for (int r = 0; r < ALa; r++) {
        int idx = t + r*128;
        int j = idx >> 7, d = idx & 127;
        ak[j][d] = g_ak[(size_t)(b*ALa + j) * Dd + h*HDh + d];
        av[j][d] = g_av[(size_t)(b*ALa + j) * Dd + h*HDh + d];
    }
    __syncthreads();

    const int w = t >> 5, lane = t & 31;
    const int s = s0 + w;
    const size_t base = (size_t)(b*Ss + s) * Dd + h*HDh;
    const float rscale = 0.08838834764831844f;

    float4 qv = *(const float4*)&g_q[base + lane*4];
    float sc[ALa];
    #pragma unroll
    for (int j = 0; j < ALa; j++) {
        float d0 = qv.x*ak[j][lane*4+0] + qv.y*ak[j][lane*4+1]
                 + qv.z*ak[j][lane*4+2] + qv.w*ak[j][lane*4+3];
        #pragma unroll
        for (int off = 16; off >= 1; off >>= 1)
            d0 += __shfl_xor_sync(0xffffffffu, d0, off);
        sc[j] = d0 * rscale;
    }
    float mx = sc[0];
    #pragma unroll
    for (int j = 1; j < ALa; j++) mx = fmaxf(mx, sc[j]);
    float sum = 0.f;
    #pragma unroll
    for (int j = 0; j < ALa; j++) { sc[j] = __expf(sc[j] - mx); sum += sc[j]; }
    float inv = 1.f / sum;
    float gg = tanhf(gate[h]);

    float acc[4] = {0.f, 0.f, 0.f, 0.f};
    #pragma unroll
    for (int j = 0; j < ALa; j++) {
        float p = sc[j] * inv;
        acc[0] += p * av[j][lane*4+0];
        acc[1] += p * av[j][lane*4+1];
        acc[2] += p * av[j][lane*4+2];
        acc[3] += p * av[j][lane*4+3];
    }
    float4 ov = *(float4*)&g_attn[base + lane*4];
    ov.x += gg*acc[0]; ov.y += gg*acc[1]; ov.z += gg*acc[2]; ov.w += gg*acc[3];
    *(float4*)&g_attn[base + lane*4] = ov;
}

// ---------------- host ----------------
extern "C" void kernel_launch(void* const* d_in, const int* in_sizes, int n_in,
                              void* d_out, int out_size)
{
    (void)in_sizes; (void)n_in; (void)out_size;
    const float* x       = (const float*)d_in[0];
    const float* cosT    = (const float*)d_in[2];
    const float* sinT    = (const float*)d_in[3];
    const float* wq      = (const float*)d_in[4];
    const float* wk      = (const float*)d_in[5];
    const float* wv      = (const float*)d_in[6];
    const float* wo      = (const float*)d_in[7];
    const float* gate    = (const float*)d_in[8];
    const float* adapter = (const float*)d_in[9];
    float* out = (float*)d_out;

    float *qp, *kp, *vp, *attnp;
    cudaGetSymbolAddress((void**)&qp,    g_q);
    cudaGetSymbolAddress((void**)&kp,    g_k);
    cudaGetSymbolAddress((void**)&vp,    g_v);
    cudaGetSymbolAddress((void**)&attnp, g_attn);

    cudaFuncSetAttribute(gemm_mma, cudaFuncAttributeMaxDynamicSharedMemorySize, GEMM_SMEM);
    cudaFuncSetAttribute(flash_mma, cudaFuncAttributeMaxDynamicSharedMemorySize, FLASH_SMEM);

    dim3 gbig(Dd/BN, Mtok/BM);

    gemm_mma<<<gbig, 256, GEMM_SMEM>>>(x, wq, qp, Mtok, Dd, Dd);
    gemm_mma<<<gbig, 256, GEMM_SMEM>>>(x, wk, kp, Mtok, Dd, Dd);
    gemm_mma<<<gbig, 256, GEMM_SMEM>>>(x, wv, vp, Mtok, Dd, Dd);

    gemm_skinny<<<dim3(Dd/128, KSPL, 2), 128>>>(adapter, wk, wv);
    skinny_reduce<<<(20*4096 + 255)/256, 256>>>();

    int npairs = Bb*Ss*Hh*HALFh;
    rope_kernel<<<npairs/256, 256>>>(qp, cosT, sinT);
    rope_kernel<<<npairs/256, 256>>>(kp, cosT, sinT);

    flash_mma<<<dim3(Ss/FQ, Bb*Hh), 256, FLASH_SMEM>>>();
    adapter_kernel<<<dim3(Ss/4, Bb*Hh), 128>>>(gate);

    gemm_mma<<<gbig, 256, GEMM_SMEM>>>(attnp, wo, out, Mtok, Dd, Dd);
}

// round 8
// speedup vs baseline: 1.7301x; 1.7301x over previous
#include <cuda_runtime.h>
#include <cuda_fp16.h>
#include <math.h>
#include <stdint.h>

#define Bb 2
#define Ss 2048
#define Dd 4096
#define Hh 32
#define HDh 128
#define HALFh 64
#define ALa 10
#define Mtok (Bb*Ss)

// ---- fp16x3 GEMM config ----
#define BM 128
#define BN 128
#define BKh 64                       // halves per K-chunk = 128B row
#define HROWB 144                    // smem row bytes (128 data + 16 pad)
#define STAGE_OPB (128*HROWB)        // one operand per stage = 18432 B
#define STAGE_B (2*STAGE_OPB)
#define NSTAGE 4
#define GEMM_SMEM (NSTAGE*STAGE_B)   // 147456

// ---- flash config ----
#define FQ 128
#define FKV 64
#define FROWB 272                    // 128 halves + 8 pad = 272 B
#define QHOFF 0
#define QLOFF (128*FROWB)
#define KHOFF (QLOFF + 128*FROWB)
#define KLOFF (KHOFF + 64*FROWB)
#define VHOFF (KLOFF + 64*FROWB)
#define VLOFF (VHOFF + 64*FROWB)
#define FLASH_SMEM (VLOFF + 64*FROWB)   // 139264 B

#define KSPL 8

// ---------------- scratch (static device globals) ----------------
__device__ float g_q[Mtok*Dd];
__device__ float g_k[Mtok*Dd];
__device__ float g_v[Mtok*Dd];
__device__ float g_attn[Mtok*Dd];
__device__ float g_ak[Bb*ALa*Dd];
__device__ float g_av[Bb*ALa*Dd];
__device__ float g_pk[KSPL*Bb*ALa*Dd];
__device__ float g_pv[KSPL*Bb*ALa*Dd];

__device__ __half g_ah[Mtok*Dd];   // x split (reused later for attn split)
__device__ __half g_al[Mtok*Dd];
__device__ __half g_wqh[Dd*Dd], g_wql[Dd*Dd];
__device__ __half g_wkh[Dd*Dd], g_wkl[Dd*Dd];
__device__ __half g_wvh[Dd*Dd], g_wvl[Dd*Dd];
__device__ __half g_woh[Dd*Dd], g_wol[Dd*Dd];
__device__ __half g_qh[Mtok*Dd], g_ql[Mtok*Dd];
__device__ __half g_kh[Mtok*Dd], g_kl[Mtok*Dd];
__device__ __half g_vh[Mtok*Dd], g_vl[Mtok*Dd];

// ---------------- helpers ----------------
__device__ __forceinline__ uint32_t s2u(const void* p){
    uint32_t r;
    asm("{ .reg .u64 t; cvta.to.shared.u64 t, %1; cvt.u32.u64 %0, t; }" : "=r"(r) : "l"(p));
    return r;
}

__device__ __forceinline__ void ldsm_x4(uint32_t* r, uint32_t addr){
    asm volatile("ldmatrix.sync.aligned.m8n8.x4.shared.b16 {%0,%1,%2,%3}, [%4];"
                 : "=r"(r[0]), "=r"(r[1]), "=r"(r[2]), "=r"(r[3]) : "r"(addr));
}
__device__ __forceinline__ void ldsm_x4t(uint32_t* r, uint32_t addr){
    asm volatile("ldmatrix.sync.aligned.m8n8.x4.trans.shared.b16 {%0,%1,%2,%3}, [%4];"
                 : "=r"(r[0]), "=r"(r[1]), "=r"(r[2]), "=r"(r[3]) : "r"(addr));
}

__device__ __forceinline__ void mma_h(float* d, const uint32_t* a, uint32_t b0, uint32_t b1){
    asm volatile(
        "mma.sync.aligned.m16n8k16.row.col.f32.f16.f16.f32 "
        "{%0,%1,%2,%3}, {%4,%5,%6,%7}, {%8,%9}, {%0,%1,%2,%3};"
        : "+f"(d[0]), "+f"(d[1]), "+f"(d[2]), "+f"(d[3])
        : "r"(a[0]), "r"(a[1]), "r"(a[2]), "r"(a[3]), "r"(b0), "r"(b1));
}

__device__ __forceinline__ uint32_t packh2(float lo, float hi){
    uint32_t r;
    asm("cvt.rn.f16x2.f32 %0, %1, %2;" : "=r"(r) : "f"(hi), "f"(lo));   // a->upper, b->lower
    return r;
}

// split two fp32 into packed hi-half2 and lo-half2 (lower lane = first arg)
__device__ __forceinline__ void split_pack(float f0, float f1, uint32_t& hi, uint32_t& lo){
    __half h0 = __float2half_rn(f0), h1 = __float2half_rn(f1);
    hi = packh2(__half2float(h0)*0.f + 0.f, 0.f); // placeholder overwritten below
    __half2 hh = __halves2half2(h0, h1);
    hi = *reinterpret_cast<uint32_t*>(&hh);
    lo = packh2(f0 - __half2float(h0), f1 - __half2float(h1));
}

// ---------------- convert: fp32 -> fp16 hi/lo ----------------
__global__ void conv_split(const float* __restrict__ s, __half* __restrict__ hi,
                           __half* __restrict__ lo, int n)
{
    int i = (blockIdx.x*256 + threadIdx.x) * 4;
    if (i >= n) return;
    float4 v = *(const float4*)(s + i);
    __half h0 = __float2half_rn(v.x), h1 = __float2half_rn(v.y);
    __half h2 = __float2half_rn(v.z), h3 = __float2half_rn(v.w);
    *(__half2*)(hi + i)     = __halves2half2(h0, h1);
    *(__half2*)(hi + i + 2) = __halves2half2(h2, h3);
    *(__half2*)(lo + i)     = __halves2half2(__float2half_rn(v.x - __half2float(h0)),
                                             __float2half_rn(v.y - __half2float(h1)));
    *(__half2*)(lo + i + 2) = __halves2half2(__float2half_rn(v.z - __half2float(h2)),
                                             __float2half_rn(v.w - __half2float(h3)));
}

// ---------------- fp16x3 NT GEMM: C = A @ B^T via [Ah|Al|Ah] x [Bh|Bh|Bl] ----------------
__global__ __launch_bounds__(256) void gemm_h3(
    const __half* __restrict__ Ah, const __half* __restrict__ Al,
    const __half* __restrict__ Bh, const __half* __restrict__ Bl,
    float* __restrict__ C, int M, int N, int K)
{
    extern __shared__ char smg[];
    const uint32_t sbase = s2u(smg);
    const int t = threadIdx.x;
    const int m0 = blockIdx.y * BM;
    const int n0 = blockIdx.x * BN;
    const int NCHP = K / BKh;            // chunks per pass (64 for K=4096)
    const int NCH = 3 * NCHP;

    const int lane = t & 31;
    const int wid  = t >> 5;
    const int wm   = wid & 3;            // 4 warps along M
    const int wn   = wid >> 2;           // 2 warps along N

    float d[2][8][4];
    #pragma unroll
    for (int mt = 0; mt < 2; mt++)
        #pragma unroll
        for (int nt = 0; nt < 8; nt++)
            #pragma unroll
            for (int c = 0; c < 4; c++) d[mt][nt][c] = 0.f;

    // ldmatrix lane addressing (byte offsets within stage operand)
    const uint32_t aRow = (uint32_t)(wm*32 + (lane & 7) + ((lane >> 3) & 1)*8);
    const uint32_t aKof = (uint32_t)(((lane >> 4) & 1) << 4);
    const uint32_t bRow = (uint32_t)(wn*64 + (lane & 7) + ((lane >> 4) & 1)*8);
    const uint32_t bKof = (uint32_t)(((lane >> 3) & 1) << 4);

    const int ldr = t >> 3;      // 0..31  (row block per cp.async iter)
    const int ldq = t & 7;       // 16B chunk within 128B row

    auto prefetch = [&](int chunk, int stage){
        const int pass = chunk / NCHP;
        const int k0 = (chunk - pass*NCHP) * BKh;
        const __half* As = (pass == 1) ? Al : Ah;
        const __half* Bs = (pass == 2) ? Bl : Bh;
        const uint32_t sA = sbase + (uint32_t)stage * STAGE_B;
        const uint32_t sB = sA + STAGE_OPB;
        #pragma unroll
        for (int i = 0; i < 4; i++) {
            int row = ldr + i*32;
            int ar = m0 + row; if (ar > M-1) ar = M-1;
            const __half* ga = As + (size_t)ar * K + k0 + ldq*8;
            const __half* gb = Bs + (size_t)(n0 + row) * K + k0 + ldq*8;
            uint32_t so = (uint32_t)row * HROWB + (uint32_t)ldq * 16u;
            asm volatile("cp.async.cg.shared.global [%0], [%1], 16;" :: "r"(sA + so), "l"(ga));
            asm volatile("cp.async.cg.shared.global [%0], [%1], 16;" :: "r"(sB + so), "l"(gb));
        }
        asm volatile("cp.async.commit_group;" ::: "memory");
    };

    #pragma unroll
    for (int p = 0; p < NSTAGE; p++) prefetch(p, p);

    for (int n = 0; n < NCH; n++) {
        const int s = n & (NSTAGE - 1);
        asm volatile("cp.async.wait_group %0;" :: "n"(NSTAGE-1) : "memory");
        __syncthreads();

        const uint32_t sA = sbase + (uint32_t)s * STAGE_B;
        const uint32_t sB = sA + STAGE_OPB;

        #pragma unroll
        for (int ks = 0; ks < 4; ks++) {       // 4 k16-steps per 64-half chunk
            const uint32_t kb = (uint32_t)ks * 32u;
            uint32_t af[2][4];
            #pragma unroll
            for (int mt = 0; mt < 2; mt++)
                ldsm_x4(af[mt], sA + (aRow + mt*16u)*HROWB + aKof + kb);
            #pragma unroll
            for (int np = 0; np < 4; np++) {
                uint32_t bf[4];
                ldsm_x4(bf, sB + (bRow + np*16u)*HROWB + bKof + kb);
                #pragma unroll
                for (int mt = 0; mt < 2; mt++) {
                    mma_h(d[mt][2*np],   af[mt], bf[0], bf[1]);
                    mma_h(d[mt][2*np+1], af[mt], bf[2], bf[3]);
                }
            }
        }
        __syncthreads();

        int pn = n + NSTAGE; if (pn >= NCH) pn = 0;
        prefetch(pn, s);
    }

    const int g  = lane >> 2;
    const int tq = lane & 3;
    #pragma unroll
    for (int mt = 0; mt < 2; mt++) {
        int row = m0 + wm*32 + mt*16 + g;
        #pragma unroll
        for (int nt = 0; nt < 8; nt++) {
            int col = n0 + wn*64 + nt*8 + 2*tq;
            if (row < M)
                *(float2*)&C[(size_t)row * N + col] = make_float2(d[mt][nt][0], d[mt][nt][1]);
            if (row + 8 < M)
                *(float2*)&C[(size_t)(row+8) * N + col] = make_float2(d[mt][nt][2], d[mt][nt][3]);
        }
    }
}

// ---------------- skinny adapter GEMM (M=20, fp32, split-K) ----------------
__global__ __launch_bounds__(128) void gemm_skinny(
    const float* __restrict__ Aad, const float* __restrict__ wk, const float* __restrict__ wv)
{
    __shared__ float As[20][33];
    __shared__ float Bs[128][33];
    const int t = threadIdx.x;
    const int n0 = blockIdx.x * 128;
    const int kz = blockIdx.y;
    const float* W = blockIdx.z ? wv : wk;
    float* P = (blockIdx.z ? g_pv : g_pk) + (size_t)kz * (20*4096);

    float acc[20];
    #pragma unroll
    for (int m = 0; m < 20; m++) acc[m] = 0.f;

    for (int k0 = kz*512; k0 < kz*512 + 512; k0 += 32) {
        for (int i = t; i < 640; i += 128) {
            int r = i >> 5, c = i & 31;
            As[r][c] = Aad[(size_t)r*4096 + k0 + c];
        }
        #pragma unroll
        for (int i = 0; i < 8; i++) {
            int idx = t + i*128;
            int r = idx >> 3, cq = idx & 7;
            float4 v = *(const float4*)&W[(size_t)(n0 + r)*4096 + k0 + cq*4];
            Bs[r][cq*4+0] = v.x; Bs[r][cq*4+1] = v.y;
            Bs[r][cq*4+2] = v.z; Bs[r][cq*4+3] = v.w;
        }
        __syncthreads();
        #pragma unroll
        for (int k = 0; k < 32; k++) {
            float bv = Bs[t][k];
            #pragma unroll
            for (int m = 0; m < 20; m++) acc[m] += As[m][k] * bv;
        }
        __syncthreads();
    }
    #pragma unroll
    for (int m = 0; m < 20; m++) P[(size_t)m*4096 + n0 + t] = acc[m];
}

__global__ void skinny_reduce()
{
    int i = blockIdx.x*256 + threadIdx.x;
    if (i >= 20*4096) return;
    float sk = 0.f, sv = 0.f;
    #pragma unroll
    for (int z = 0; z < KSPL; z++) {
        sk += g_pk[(size_t)z*(20*4096) + i];
        sv += g_pv[(size_t)z*(20*4096) + i];
    }
    g_ak[i] = sk;
    g_av[i] = sv;
}

// ---------------- RoPE (fp32 in place) + split to fp16 hi/lo ----------------
__global__ void rope_split(float* __restrict__ T, __half* __restrict__ Th, __half* __restrict__ Tl,
                           const float* __restrict__ cosT, const float* __restrict__ sinT)
{
    int idx = blockIdx.x * blockDim.x + threadIdx.x;   // pair index
    if (idx >= Bb*Ss*Hh*HALFh) return;
    int p = idx & (HALFh - 1);
    int s = (idx >> 11) & (Ss - 1);
    float c  = cosT[s*HALFh + p];
    float sn = sinT[s*HALFh + p];
    float2 v = *(float2*)&T[2*(size_t)idx];
    float2 r;
    r.x = v.x * c - v.y * sn;
    r.y = v.x * sn + v.y * c;
    *(float2*)&T[2*(size_t)idx] = r;
    __half h0 = __float2half_rn(r.x), h1 = __float2half_rn(r.y);
    *(__half2*)(Th + 2*(size_t)idx) = __halves2half2(h0, h1);
    *(__half2*)(Tl + 2*(size_t)idx) = __halves2half2(__float2half_rn(r.x - __half2float(h0)),
                                                     __float2half_rn(r.y - __half2float(h1)));
}

// ---------------- flash attention via fp16x3 mma.sync ----------------
// grid (S/FQ, B*H), 256 threads, 8 warps, 16 q-rows per warp.
__global__ __launch_bounds__(256, 1) void flash_h()
{
    extern __shared__ char fsm[];
    const uint32_t sb = s2u(fsm);
    const int t = threadIdx.x, lane = t & 31, w = t >> 5;
    const int bh = blockIdx.y, b = bh >> 5, h = bh & 31;
    const int q0 = (int)(gridDim.x - 1 - blockIdx.x) * FQ;
    const size_t headbase = (size_t)b * Ss * Dd + (size_t)h * HDh;
    const int g = lane >> 2, tq = lane & 3;
    const float rscale = 0.08838834764831844f;
    const float NEGINF = __int_as_float(0xff800000);

    // Q (hi and lo) -> smem
    {
        const __half* qh = g_qh + headbase + (size_t)q0 * Dd;
        const __half* ql = g_ql + headbase + (size_t)q0 * Dd;
        #pragma unroll
        for (int i = 0; i < 8; i++) {
            int idx = t + i*256;
            int r = idx >> 4, cq = idx & 15;
            asm volatile("cp.async.cg.shared.global [%0], [%1], 16;"
                :: "r"(sb + QHOFF + (uint32_t)(r*FROWB + cq*16)), "l"(qh + (size_t)r*Dd + cq*8));
            asm volatile("cp.async.cg.shared.global [%0], [%1], 16;"
                :: "r"(sb + QLOFF + (uint32_t)(r*FROWB + cq*16)), "l"(ql + (size_t)r*Dd + cq*8));
        }
        asm volatile("cp.async.commit_group;" ::: "memory");
    }

    // lane addressing
    const uint32_t aRow = (uint32_t)(w*16 + (lane & 7) + ((lane >> 3) & 1)*8);
    const uint32_t aKof = (uint32_t)(((lane >> 4) & 1) << 4);
    const uint32_t bRow = (uint32_t)((lane & 7) + ((lane >> 4) & 1)*8);
    const uint32_t bKof = (uint32_t)(((lane >> 3) & 1) << 4);
    const uint32_t vRow = (uint32_t)((lane & 7) + ((lane >> 3) & 1)*8);
    const uint32_t vDof = (uint32_t)(((lane >> 4) & 1) << 4);

    float o[16][4];
    #pragma unroll
    for (int nt = 0; nt < 16; nt++) { o[nt][0]=o[nt][1]=o[nt][2]=o[nt][3]=0.f; }
    float m0r = -1e30f, m1r = -1e30f, l0r = 0.f, l1r = 0.f;

    const int ig0 = q0 + w*16 + g;
    const int ig1 = ig0 + 8;

    for (int j0 = 0; j0 < q0 + FQ; j0 += FKV) {
        __syncthreads();
        {
            const __half* kh = g_kh + headbase + (size_t)j0 * Dd;
            const __half* kl = g_kl + headbase + (size_t)j0 * Dd;
            const __half* vh = g_vh + headbase + (size_t)j0 * Dd;
            const __half* vl = g_vl + headbase + (size_t)j0 * Dd;
            #pragma unroll
            for (int i = 0; i < 4; i++) {
                int idx = t + i*256;
                int r = idx >> 4, cq = idx & 15;
                uint32_t so = (uint32_t)(r*FROWB + cq*16);
                size_t go = (size_t)r*Dd + cq*8;
                asm volatile("cp.async.cg.shared.global [%0], [%1], 16;" :: "r"(sb + KHOFF + so), "l"(kh + go));
                asm volatile("cp.async.cg.shared.global [%0], [%1], 16;" :: "r"(sb + KLOFF + so), "l"(kl + go));
                asm volatile("cp.async.cg.shared.global [%0], [%1], 16;" :: "r"(sb + VHOFF + so), "l"(vh + go));
                asm volatile("cp.async.cg.shared.global [%0], [%1], 16;" :: "r"(sb + VLOFF + so), "l"(vl + go));
            }
            asm volatile("cp.async.commit_group;" ::: "memory");
        }
        asm volatile("cp.async.wait_group 0;" ::: "memory");
        __syncthreads();

        // ---- S = Q K^T : hi*hi + hi*lo + lo*hi ----
        float s[8][4];
        #pragma unroll
        for (int nt = 0; nt < 8; nt++) { s[nt][0]=s[nt][1]=s[nt][2]=s[nt][3]=0.f; }
        #pragma unroll
        for (int ks = 0; ks < 8; ks++) {
            const uint32_t kb = (uint32_t)ks * 32u;
            uint32_t ah[4], al_[4];
            ldsm_x4(ah,  sb + QHOFF + aRow*FROWB + aKof + kb);
            ldsm_x4(al_, sb + QLOFF + aRow*FROWB + aKof + kb);
            #pragma unroll
            for (int np = 0; np < 4; np++) {
                uint32_t bhf[4], blf[4];
                ldsm_x4(bhf, sb + KHOFF + (bRow + np*16u)*FROWB + bKof + kb);
                ldsm_x4(blf, sb + KLOFF + (bRow + np*16u)*FROWB + bKof + kb);
                mma_h(s[2*np],   ah,  bhf[0], bhf[1]);
                mma_h(s[2*np],   ah,  blf[0], blf[1]);
                mma_h(s[2*np],   al_, bhf[0], bhf[1]);
                mma_h(s[2*np+1], ah,  bhf[2], bhf[3]);
                mma_h(s[2*np+1], ah,  blf[2], blf[3]);
                mma_h(s[2*np+1], al_, bhf[2], bhf[3]);
            }
        }

        // ---- mask + online softmax (accumulator rows g, g+8; cols nt*8+2tq) ----
        float mx0 = -1e30f, mx1 = -1e30f;
        #pragma unroll
        for (int nt = 0; nt < 8; nt++) {
            int jg = j0 + nt*8 + 2*tq;
            s[nt][0] = (jg   > ig0) ? NEGINF : s[nt][0]*rscale;
            s[nt][1] = (jg+1 > ig0) ? NEGINF : s[nt][1]*rscale;
            s[nt][2] = (jg   > ig1) ? NEGINF : s[nt][2]*rscale;
            s[nt][3] = (jg+1 > ig1) ? NEGINF : s[nt][3]*rscale;
            mx0 = fmaxf(mx0, fmaxf(s[nt][0], s[nt][1]));
            mx1 = fmaxf(mx1, fmaxf(s[nt][2], s[nt][3]));
        }
        mx0 = fmaxf(mx0, __shfl_xor_sync(0xffffffffu, mx0, 1));
        mx0 = fmaxf(mx0, __shfl_xor_sync(0xffffffffu, mx0, 2));
        mx1 = fmaxf(mx1, __shfl_xor_sync(0xffffffffu, mx1, 1));
        mx1 = fmaxf(mx1, __shfl_xor_sync(0xffffffffu, mx1, 2));
        float mn0 = fmaxf(m0r, mx0), mn1 = fmaxf(m1r, mx1);
        float co0 = __expf(m0r - mn0), co1 = __expf(m1r - mn1);
        float sum0 = 0.f, sum1 = 0.f;
        #pragma unroll
        for (int nt = 0; nt < 8; nt++) {
            s[nt][0] = __expf(s[nt][0] - mn0);
            s[nt][1] = __expf(s[nt][1] - mn0);
            s[nt][2] = __expf(s[nt][2] - mn1);
            s[nt][3] = __expf(s[nt][3] - mn1);
            sum0 += s[nt][0] + s[nt][1];
            sum1 += s[nt][2] + s[nt][3];
        }
        sum0 += __shfl_xor_sync(0xffffffffu, sum0, 1);
        sum0 += __shfl_xor_sync(0xffffffffu, sum0, 2);
        sum1 += __shfl_xor_sync(0xffffffffu, sum1, 1);
        sum1 += __shfl_xor_sync(0xffffffffu, sum1, 2);
        l0r = l0r * co0 + sum0;  m0r = mn0;
        l1r = l1r * co1 + sum1;  m1r = mn1;

        #pragma unroll
        for (int nt = 0; nt < 16; nt++) {
            o[nt][0] *= co0; o[nt][1] *= co0;
            o[nt][2] *= co1; o[nt][3] *= co1;
        }

        // ---- O += P V : phi*vhi + phi*vlo + plo*vhi (P packed in-register) ----
        #pragma unroll
        for (int ks = 0; ks < 4; ks++) {
            uint32_t ph[4], pl[4];
            split_pack(s[2*ks][0],   s[2*ks][1],   ph[0], pl[0]);
            split_pack(s[2*ks][2],   s[2*ks][3],   ph[1], pl[1]);
            split_pack(s[2*ks+1][0], s[2*ks+1][1], ph[2], pl[2]);
            split_pack(s[2*ks+1][2], s[2*ks+1][3], ph[3], pl[3]);
            const uint32_t krow = (uint32_t)(ks*16) + vRow;
            #pragma unroll
            for (int np = 0; np < 8; np++) {
                uint32_t vhf[4], vlf[4];
                ldsm_x4t(vhf, sb + VHOFF + krow*FROWB + (uint32_t)(np*32) + vDof);
                ldsm_x4t(vlf, sb + VLOFF + krow*FROWB + (uint32_t)(np*32) + vDof);
                mma_h(o[2*np],   ph, vhf[0], vhf[1]);
                mma_h(o[2*np],   ph, vlf[0], vlf[1]);
                mma_h(o[2*np],   pl, vhf[0], vhf[1]);
                mma_h(o[2*np+1], ph, vhf[2], vhf[3]);
                mma_h(o[2*np+1], ph, vlf[2], vlf[3]);
                mma_h(o[2*np+1], pl, vhf[2], vhf[3]);
            }
        }
    }

    float inv0 = 1.f / l0r, inv1 = 1.f / l1r;
    float* Og = g_attn + headbase + (size_t)(q0 + w*16) * Dd;
    #pragma unroll
    for (int nt = 0; nt < 16; nt++) {
        *(float2*)&Og[(size_t)g*Dd     + nt*8 + 2*tq] = make_float2(o[nt][0]*inv0, o[nt][1]*inv0);
        *(float2*)&Og[(size_t)(g+8)*Dd + nt*8 + 2*tq] = make_float2(o[nt][2]*inv1, o[nt][3]*inv1);
    }
}

// ---------------- adapter attention ----------------
__global__ __launch_bounds__(128) void adapter_kernel(const float* __restrict__ gate)
{
    __shared__ __align__(16) float ak[ALa][HDh];
    __shared__ __align__(16) float av[ALa][HDh];
    const int t = threadIdx.x;
    const int bh = blockIdx.y;
    const int b = bh >> 5, h = bh & 31;
    const int s0 = blockIdx.x * 4;

    #pragma unroll
    for (int r = 0; r < ALa; r++) {
        int idx = t + r*128;
        int j = idx >> 7, d = idx & 127;
        ak[j][d] = g_ak[(size_t)(b*ALa + j) * Dd + h*HDh + d];
        av[j][d] = g_av[(size_t)(b*ALa + j) * Dd + h*HDh + d];
    }
    __syncthreads();

    const int w = t >> 5, lane = t & 31;
    const int s = s0 + w;
    const size_t base = (size_t)(b*Ss + s) * Dd + h*HDh;
    const float rscale = 0.08838834764831844f;

    float4 qv = *(const float4*)&g_q[base + lane*4];
    float sc[ALa];
    #pragma unroll
    for (int j = 0; j < ALa; j++) {
        float d0 = qv.x*ak[j][lane*4+0] + qv.y*ak[j][lane*4+1]
                 + qv.z*ak[j][lane*4+2] + qv.w*ak[j][lane*4+3];
        #pragma unroll
        for (int off = 16; off >= 1; off >>= 1)
            d0 += __shfl_xor_sync(0xffffffffu, d0, off);
        sc[j] = d0 * rscale;
    }
    float mx = sc[0];
    #pragma unroll
    for (int j = 1; j < ALa; j++) mx = fmaxf(mx, sc[j]);
    float sum = 0.f;
    #pragma unroll
    for (int j = 0; j < ALa; j++) { sc[j] = __expf(sc[j] - mx); sum += sc[j]; }
    float inv = 1.f / sum;
    float gg = tanhf(gate[h]);

    float acc[4] = {0.f, 0.f, 0.f, 0.f};
    #pragma unroll
    for (int j = 0; j < ALa; j++) {
        float p = sc[j] * inv;
        acc[0] += p * av[j][lane*4+0];
        acc[1] += p * av[j][lane*4+1];
        acc[2] += p * av[j][lane*4+2];
        acc[3] += p * av[j][lane*4+3];
    }
    float4 ov = *(float4*)&g_attn[base + lane*4];
    ov.x += gg*acc[0]; ov.y += gg*acc[1]; ov.z += gg*acc[2]; ov.w += gg*acc[3];
    *(float4*)&g_attn[base + lane*4] = ov;
}

// ---------------- host ----------------
extern "C" void kernel_launch(void* const* d_in, const int* in_sizes, int n_in,
                              void* d_out, int out_size)
{
    (void)in_sizes; (void)n_in; (void)out_size;
    const float* x       = (const float*)d_in[0];
    const float* cosT    = (const float*)d_in[2];
    const float* sinT    = (const float*)d_in[3];
    const float* wq      = (const float*)d_in[4];
    const float* wk      = (const float*)d_in[5];
    const float* wv      = (const float*)d_in[6];
    const float* wo      = (const float*)d_in[7];
    const float* gate    = (const float*)d_in[8];
    const float* adapter = (const float*)d_in[9];
    float* out = (float*)d_out;

    float *qp, *kp, *vp, *attnp;
    __half *ahp, *alp, *wqh, *wql, *wkh, *wkl, *wvh, *wvl, *woh, *wol;
    __half *qhp, *qlp, *khp, *klp, *vhp, *vlp;
    cudaGetSymbolAddress((void**)&qp,    g_q);
    cudaGetSymbolAddress((void**)&kp,    g_k);
    cudaGetSymbolAddress((void**)&vp,    g_v);
    cudaGetSymbolAddress((void**)&attnp, g_attn);
    cudaGetSymbolAddress((void**)&ahp,  g_ah);  cudaGetSymbolAddress((void**)&alp,  g_al);
    cudaGetSymbolAddress((void**)&wqh,  g_wqh); cudaGetSymbolAddress((void**)&wql,  g_wql);
    cudaGetSymbolAddress((void**)&wkh,  g_wkh); cudaGetSymbolAddress((void**)&wkl,  g_wkl);
    cudaGetSymbolAddress((void**)&wvh,  g_wvh); cudaGetSymbolAddress((void**)&wvl,  g_wvl);
    cudaGetSymbolAddress((void**)&woh,  g_woh); cudaGetSymbolAddress((void**)&wol,  g_wol);
    cudaGetSymbolAddress((void**)&qhp,  g_qh);  cudaGetSymbolAddress((void**)&qlp,  g_ql);
    cudaGetSymbolAddress((void**)&khp,  g_kh);  cudaGetSymbolAddress((void**)&klp,  g_kl);
    cudaGetSymbolAddress((void**)&vhp,  g_vh);  cudaGetSymbolAddress((void**)&vlp,  g_vl);

    cudaFuncSetAttribute(gemm_h3, cudaFuncAttributeMaxDynamicSharedMemorySize, GEMM_SMEM);
    cudaFuncSetAttribute(flash_h, cudaFuncAttributeMaxDynamicSharedMemorySize, FLASH_SMEM);

    const int nXW = Mtok*Dd;          // == Dd*Dd
    const int cgrid = nXW/4/256;

    conv_split<<<cgrid, 256>>>(x,  ahp, alp, nXW);
    conv_split<<<cgrid, 256>>>(wq, wqh, wql, Dd*Dd);
    conv_split<<<cgrid, 256>>>(wk, wkh, wkl, Dd*Dd);
    conv_split<<<cgrid, 256>>>(wv, wvh, wvl, Dd*Dd);
    conv_split<<<cgrid, 256>>>(wo, woh, wol, Dd*Dd);

    dim3 gbig(Dd/BN, Mtok/BM);
    gemm_h3<<<gbig, 256, GEMM_SMEM>>>(ahp, alp, wqh, wql, qp, Mtok, Dd, Dd);
    gemm_h3<<<gbig, 256, GEMM_SMEM>>>(ahp, alp, wkh, wkl, kp, Mtok, Dd, Dd);
    gemm_h3<<<gbig, 256, GEMM_SMEM>>>(ahp, alp, wvh, wvl, vp, Mtok, Dd, Dd);

    gemm_skinny<<<dim3(Dd/128, KSPL, 2), 128>>>(adapter, wk, wv);
    skinny_reduce<<<(20*4096 + 255)/256, 256>>>();

    int npairs = Bb*Ss*Hh*HALFh;
    rope_split<<<npairs/256, 256>>>(qp, qhp, qlp, cosT, sinT);
    rope_split<<<npairs/256, 256>>>(kp, khp, klp, cosT, sinT);
    conv_split<<<cgrid, 256>>>(vp, vhp, vlp, nXW);

    flash_h<<<dim3(Ss/FQ, Bb*Hh), 256, FLASH_SMEM>>>();
    adapter_kernel<<<dim3(Ss/4, Bb*Hh), 128>>>(gate);

    conv_split<<<cgrid, 256>>>(attnp, ahp, alp, nXW);   // reuse x-split buffers
    gemm_h3<<<gbig, 256, GEMM_SMEM>>>(ahp, alp, woh, wol, out, Mtok, Dd, Dd);
}

// round 9
// speedup vs baseline: 2.0510x; 1.1855x over previous
#include <cuda_runtime.h>
#include <cuda_fp16.h>
#include <math.h>
#include <stdint.h>

#define Bb 2
#define Ss 2048
#define Dd 4096
#define Hh 32
#define HDh 128
#define HALFh 64
#define ALa 10
#define Mtok (Bb*Ss)

// ---- fused fp16x3 GEMM config ----
#define BM 128
#define BN 128
#define BKh 64                       // halves per K-chunk = 128B row
#define HROWB 144                    // smem row bytes (128 data + 16 pad)
#define OPB (128*HROWB)              // one operand = 18432 B
#define STAGE_B (4*OPB)              // Ah, Al, Bh, Bl = 73728 B
#define NSTAGE 3
#define GEMM_SMEM (NSTAGE*STAGE_B)   // 221184 B

// ---- flash config ----
#define FQ 128
#define FKV 64
#define FROWB 272                    // 128 halves + 8 pad = 272 B
#define QHOFF 0
#define QLOFF (128*FROWB)
#define KHOFF (QLOFF + 128*FROWB)
#define KLOFF (KHOFF + 64*FROWB)
#define VHOFF (KLOFF + 64*FROWB)
#define VLOFF (VHOFF + 64*FROWB)
#define FLASH_SMEM (VLOFF + 64*FROWB)   // 139264 B

#define KSPL 8

// ---------------- scratch (static device globals) ----------------
__device__ float g_q[Mtok*Dd];
__device__ float g_k[Mtok*Dd];
__device__ float g_v[Mtok*Dd];
__device__ float g_attn[Mtok*Dd];
__device__ float g_ak[Bb*ALa*Dd];
__device__ float g_av[Bb*ALa*Dd];
__device__ float g_pk[KSPL*Bb*ALa*Dd];
__device__ float g_pv[KSPL*Bb*ALa*Dd];

__device__ __half g_ah[Mtok*Dd];   // x split (reused later for attn split)
__device__ __half g_al[Mtok*Dd];
__device__ __half g_wqh[Dd*Dd], g_wql[Dd*Dd];
__device__ __half g_wkh[Dd*Dd], g_wkl[Dd*Dd];
__device__ __half g_wvh[Dd*Dd], g_wvl[Dd*Dd];
__device__ __half g_woh[Dd*Dd], g_wol[Dd*Dd];
__device__ __half g_qh[Mtok*Dd], g_ql[Mtok*Dd];
__device__ __half g_kh[Mtok*Dd], g_kl[Mtok*Dd];
__device__ __half g_vh[Mtok*Dd], g_vl[Mtok*Dd];

// ---------------- helpers ----------------
__device__ __forceinline__ uint32_t s2u(const void* p){
    uint32_t r;
    asm("{ .reg .u64 t; cvta.to.shared.u64 t, %1; cvt.u32.u64 %0, t; }" : "=r"(r) : "l"(p));
    return r;
}

__device__ __forceinline__ void ldsm_x4(uint32_t* r, uint32_t addr){
    asm volatile("ldmatrix.sync.aligned.m8n8.x4.shared.b16 {%0,%1,%2,%3}, [%4];"
                 : "=r"(r[0]), "=r"(r[1]), "=r"(r[2]), "=r"(r[3]) : "r"(addr));
}
__device__ __forceinline__ void ldsm_x4t(uint32_t* r, uint32_t addr){
    asm volatile("ldmatrix.sync.aligned.m8n8.x4.trans.shared.b16 {%0,%1,%2,%3}, [%4];"
                 : "=r"(r[0]), "=r"(r[1]), "=r"(r[2]), "=r"(r[3]) : "r"(addr));
}

__device__ __forceinline__ void mma_h(float* d, const uint32_t* a, uint32_t b0, uint32_t b1){
    asm volatile(
        "mma.sync.aligned.m16n8k16.row.col.f32.f16.f16.f32 "
        "{%0,%1,%2,%3}, {%4,%5,%6,%7}, {%8,%9}, {%0,%1,%2,%3};"
        : "+f"(d[0]), "+f"(d[1]), "+f"(d[2]), "+f"(d[3])
        : "r"(a[0]), "r"(a[1]), "r"(a[2]), "r"(a[3]), "r"(b0), "r"(b1));
}

__device__ __forceinline__ uint32_t packh2(float lo, float hi){
    uint32_t r;
    asm("cvt.rn.f16x2.f32 %0, %1, %2;" : "=r"(r) : "f"(hi), "f"(lo));
    return r;
}

__device__ __forceinline__ void split_pack(float f0, float f1, uint32_t& hi, uint32_t& lo){
    __half h0 = __float2half_rn(f0), h1 = __float2half_rn(f1);
    __half2 hh = __halves2half2(h0, h1);
    hi = *reinterpret_cast<uint32_t*>(&hh);
    lo = packh2(f0 - __half2float(h0), f1 - __half2float(h1));
}

// ---------------- convert: fp32 -> fp16 hi/lo ----------------
__global__ void conv_split(const float* __restrict__ s, __half* __restrict__ hi,
                           __half* __restrict__ lo, int n)
{
    int i = (blockIdx.x*256 + threadIdx.x) * 4;
    if (i >= n) return;
    float4 v = *(const float4*)(s + i);
    __half h0 = __float2half_rn(v.x), h1 = __float2half_rn(v.y);
    __half h2 = __float2half_rn(v.z), h3 = __float2half_rn(v.w);
    *(__half2*)(hi + i)     = __halves2half2(h0, h1);
    *(__half2*)(hi + i + 2) = __halves2half2(h2, h3);
    *(__half2*)(lo + i)     = __halves2half2(__float2half_rn(v.x - __half2float(h0)),
                                             __float2half_rn(v.y - __half2float(h1)));
    *(__half2*)(lo + i + 2) = __halves2half2(__float2half_rn(v.z - __half2float(h2)),
                                             __float2half_rn(v.w - __half2float(h3)));
}

// ---------------- fused fp16x3 NT GEMM: one K pass, 3 MMA terms per fragment ----------------
__global__ __launch_bounds__(256) void gemm_h3f(
    const __half* __restrict__ Ah, const __half* __restrict__ Al,
    const __half* __restrict__ Bh, const __half* __restrict__ Bl,
    float* __restrict__ C, int M, int N, int K)
{
    extern __shared__ char smg[];
    const uint32_t sbase = s2u(smg);
    const int t = threadIdx.x;
    const int m0 = blockIdx.y * BM;
    const int n0 = blockIdx.x * BN;
    const int NCH = K / BKh;             // 64 chunks, single pass

    const int lane = t & 31;
    const int wid  = t >> 5;
    const int wm   = wid & 3;            // 4 warps along M
    const int wn   = wid >> 2;           // 2 warps along N

    float d[2][8][4];
    #pragma unroll
    for (int mt = 0; mt < 2; mt++)
        #pragma unroll
        for (int nt = 0; nt < 8; nt++)
            #pragma unroll
            for (int c = 0; c < 4; c++) d[mt][nt][c] = 0.f;

    const uint32_t aRow = (uint32_t)(wm*32 + (lane & 7) + ((lane >> 3) & 1)*8);
    const uint32_t aKof = (uint32_t)(((lane >> 4) & 1) << 4);
    const uint32_t bRow = (uint32_t)(wn*64 + (lane & 7) + ((lane >> 4) & 1)*8);
    const uint32_t bKof = (uint32_t)(((lane >> 3) & 1) << 4);

    const int ldr = t >> 3;      // 0..31
    const int ldq = t & 7;       // 16B chunk within 128B row

    auto prefetch = [&](int chunk, int stage){
        const int k0 = chunk * BKh;
        const uint32_t st = sbase + (uint32_t)stage * STAGE_B;
        #pragma unroll
        for (int i = 0; i < 4; i++) {
            int row = ldr + i*32;
            int ar = m0 + row; if (ar > M-1) ar = M-1;
            size_t goa = (size_t)ar * K + k0 + ldq*8;
            size_t gob = (size_t)(n0 + row) * K + k0 + ldq*8;
            uint32_t so = (uint32_t)row * HROWB + (uint32_t)ldq * 16u;
            asm volatile("cp.async.cg.shared.global [%0], [%1], 16;" :: "r"(st + 0*OPB + so), "l"(Ah + goa));
            asm volatile("cp.async.cg.shared.global [%0], [%1], 16;" :: "r"(st + 1*OPB + so), "l"(Al + goa));
            asm volatile("cp.async.cg.shared.global [%0], [%1], 16;" :: "r"(st + 2*OPB + so), "l"(Bh + gob));
            asm volatile("cp.async.cg.shared.global [%0], [%1], 16;" :: "r"(st + 3*OPB + so), "l"(Bl + gob));
        }
        asm volatile("cp.async.commit_group;" ::: "memory");
    };

    prefetch(0, 0);
    prefetch(1, 1);
    prefetch(2, 2);

    int stage = 0;
    for (int n = 0; n < NCH; n++) {
        asm volatile("cp.async.wait_group %0;" :: "n"(NSTAGE-1) : "memory");
        __syncthreads();

        const uint32_t st = sbase + (uint32_t)stage * STAGE_B;
        const uint32_t sAh = st, sAl = st + OPB, sBh = st + 2*OPB, sBl = st + 3*OPB;

        #pragma unroll
        for (int ks = 0; ks < 4; ks++) {       // 4 k16-steps per chunk
            const uint32_t kb = (uint32_t)ks * 32u;
            uint32_t ah[2][4], al[2][4];
            #pragma unroll
            for (int mt = 0; mt < 2; mt++) {
                ldsm_x4(ah[mt], sAh + (aRow + mt*16u)*HROWB + aKof + kb);
                ldsm_x4(al[mt], sAl + (aRow + mt*16u)*HROWB + aKof + kb);
            }
            #pragma unroll
            for (int np = 0; np < 4; np++) {
                uint32_t bh[4], bl[4];
                ldsm_x4(bh, sBh + (bRow + np*16u)*HROWB + bKof + kb);
                ldsm_x4(bl, sBl + (bRow + np*16u)*HROWB + bKof + kb);
                #pragma unroll
                for (int mt = 0; mt < 2; mt++) {
                    mma_h(d[mt][2*np],   ah[mt], bh[0], bh[1]);
                    mma_h(d[mt][2*np],   ah[mt], bl[0], bl[1]);
                    mma_h(d[mt][2*np],   al[mt], bh[0], bh[1]);
                    mma_h(d[mt][2*np+1], ah[mt], bh[2], bh[3]);
                    mma_h(d[mt][2*np+1], ah[mt], bl[2], bl[3]);
                    mma_h(d[mt][2*np+1], al[mt], bh[2], bh[3]);
                }
            }
        }
        __syncthreads();

        int pn = n + NSTAGE; if (pn >= NCH) pn = 0;
        prefetch(pn, stage);
        stage++; if (stage == NSTAGE) stage = 0;
    }

    const int g  = lane >> 2;
    const int tq = lane & 3;
    #pragma unroll
    for (int mt = 0; mt < 2; mt++) {
        int row = m0 + wm*32 + mt*16 + g;
        #pragma unroll
        for (int nt = 0; nt < 8; nt++) {
            int col = n0 + wn*64 + nt*8 + 2*tq;
            if (row < M)
                *(float2*)&C[(size_t)row * N + col] = make_float2(d[mt][nt][0], d[mt][nt][1]);
            if (row + 8 < M)
                *(float2*)&C[(size_t)(row+8) * N + col] = make_float2(d[mt][nt][2], d[mt][nt][3]);
        }
    }
}

// ---------------- skinny adapter GEMM (M=20, fp32, split-K) ----------------
__global__ __launch_bounds__(128) void gemm_skinny(
    const float* __restrict__ Aad, const float* __restrict__ wk, const float* __restrict__ wv)
{
    __shared__ float As[20][33];
    __shared__ float Bs[128][33];
    const int t = threadIdx.x;
    const int n0 = blockIdx.x * 128;
    const int kz = blockIdx.y;
    const float* W = blockIdx.z ? wv : wk;
    float* P = (blockIdx.z ? g_pv : g_pk) + (size_t)kz * (20*4096);

    float acc[20];
    #pragma unroll
    for (int m = 0; m < 20; m++) acc[m] = 0.f;

    for (int k0 = kz*512; k0 < kz*512 + 512; k0 += 32) {
        for (int i = t; i < 640; i += 128) {
            int r = i >> 5, c = i & 31;
            As[r][c] = Aad[(size_t)r*4096 + k0 + c];
        }
        #pragma unroll
        for (int i = 0; i < 8; i++) {
            int idx = t + i*128;
            int r = idx >> 3, cq = idx & 7;
            float4 v = *(const float4*)&W[(size_t)(n0 + r)*4096 + k0 + cq*4];
            Bs[r][cq*4+0] = v.x; Bs[r][cq*4+1] = v.y;
            Bs[r][cq*4+2] = v.z; Bs[r][cq*4+3] = v.w;
        }
        __syncthreads();
        #pragma unroll
        for (int k = 0; k < 32; k++) {
            float bv = Bs[t][k];
            #pragma unroll
            for (int m = 0; m < 20; m++) acc[m] += As[m][k] * bv;
        }
        __syncthreads();
    }
    #pragma unroll
    for (int m = 0; m < 20; m++) P[(size_t)m*4096 + n0 + t] = acc[m];
}

__global__ void skinny_reduce()
{
    int i = blockIdx.x*256 + threadIdx.x;
    if (i >= 20*4096) return;
    float sk = 0.f, sv = 0.f;
    #pragma unroll
    for (int z = 0; z < KSPL; z++) {
        sk += g_pk[(size_t)z*(20*4096) + i];
        sv += g_pv[(size_t)z*(20*4096) + i];
    }
    g_ak[i] = sk;
    g_av[i] = sv;
}

// ---------------- RoPE (fp32 in place) + split to fp16 hi/lo ----------------
__global__ void rope_split(float* __restrict__ T, __half* __restrict__ Th, __half* __restrict__ Tl,
                           const float* __restrict__ cosT, const float* __restrict__ sinT)
{
    int idx = blockIdx.x * blockDim.x + threadIdx.x;
    if (idx >= Bb*Ss*Hh*HALFh) return;
    int p = idx & (HALFh - 1);
    int s = (idx >> 11) & (Ss - 1);
    float c  = cosT[s*HALFh + p];
    float sn = sinT[s*HALFh + p];
    float2 v = *(float2*)&T[2*(size_t)idx];
    float2 r;
    r.x = v.x * c - v.y * sn;
    r.y = v.x * sn + v.y * c;
    *(float2*)&T[2*(size_t)idx] = r;
    __half h0 = __float2half_rn(r.x), h1 = __float2half_rn(r.y);
    *(__half2*)(Th + 2*(size_t)idx) = __halves2half2(h0, h1);
    *(__half2*)(Tl + 2*(size_t)idx) = __halves2half2(__float2half_rn(r.x - __half2float(h0)),
                                                     __float2half_rn(r.y - __half2float(h1)));
}

// ---------------- flash attention via fp16x3 mma.sync ----------------
__global__ __launch_bounds__(256, 1) void flash_h()
{
    extern __shared__ char fsm[];
    const uint32_t sb = s2u(fsm);
    const int t = threadIdx.x, lane = t & 31, w = t >> 5;
    const int bh = blockIdx.y, b = bh >> 5, h = bh & 31;
    const int q0 = (int)(gridDim.x - 1 - blockIdx.x) * FQ;
    const size_t headbase = (size_t)b * Ss * Dd + (size_t)h * HDh;
    const int g = lane >> 2, tq = lane & 3;
    const float rscale = 0.08838834764831844f;
    const float NEGINF = __int_as_float(0xff800000);

    {
        const __half* qh = g_qh + headbase + (size_t)q0 * Dd;
        const __half* ql = g_ql + headbase + (size_t)q0 * Dd;
        #pragma unroll
        for (int i = 0; i < 8; i++) {
            int idx = t + i*256;
            int r = idx >> 4, cq = idx & 15;
            asm volatile("cp.async.cg.shared.global [%0], [%1], 16;"
                :: "r"(sb + QHOFF + (uint32_t)(r*FROWB + cq*16)), "l"(qh + (size_t)r*Dd + cq*8));
            asm volatile("cp.async.cg.shared.global [%0], [%1], 16;"
                :: "r"(sb + QLOFF + (uint32_t)(r*FROWB + cq*16)), "l"(ql + (size_t)r*Dd + cq*8));
        }
        asm volatile("cp.async.commit_group;" ::: "memory");
    }

    const uint32_t aRow = (uint32_t)(w*16 + (lane & 7) + ((lane >> 3) & 1)*8);
    const uint32_t aKof = (uint32_t)(((lane >> 4) & 1) << 4);
    const uint32_t bRow = (uint32_t)((lane & 7) + ((lane >> 4) & 1)*8);
    const uint32_t bKof = (uint32_t)(((lane >> 3) & 1) << 4);
    const uint32_t vRow = (uint32_t)((lane & 7) + ((lane >> 3) & 1)*8);
    const uint32_t vDof = (uint32_t)(((lane >> 4) & 1) << 4);

    float o[16][4];
    #pragma unroll
    for (int nt = 0; nt < 16; nt++) { o[nt][0]=o[nt][1]=o[nt][2]=o[nt][3]=0.f; }
    float m0r = -1e30f, m1r = -1e30f, l0r = 0.f, l1r = 0.f;

    const int ig0 = q0 + w*16 + g;
    const int ig1 = ig0 + 8;

    for (int j0 = 0; j0 < q0 + FQ; j0 += FKV) {
        __syncthreads();
        {
            const __half* kh = g_kh + headbase + (size_t)j0 * Dd;
            const __half* kl = g_kl + headbase + (size_t)j0 * Dd;
            const __half* vh = g_vh + headbase + (size_t)j0 * Dd;
            const __half* vl = g_vl + headbase + (size_t)j0 * Dd;
            #pragma unroll
            for (int i = 0; i < 4; i++) {
                int idx = t + i*256;
                int r = idx >> 4, cq = idx & 15;
                uint32_t so = (uint32_t)(r*FROWB + cq*16);
                size_t go = (size_t)r*Dd + cq*8;
                asm volatile("cp.async.cg.shared.global [%0], [%1], 16;" :: "r"(sb + KHOFF + so), "l"(kh + go));
                asm volatile("cp.async.cg.shared.global [%0], [%1], 16;" :: "r"(sb + KLOFF + so), "l"(kl + go));
                asm volatile("cp.async.cg.shared.global [%0], [%1], 16;" :: "r"(sb + VHOFF + so), "l"(vh + go));
                asm volatile("cp.async.cg.shared.global [%0], [%1], 16;" :: "r"(sb + VLOFF + so), "l"(vl + go));
            }
            asm volatile("cp.async.commit_group;" ::: "memory");
        }
        asm volatile("cp.async.wait_group 0;" ::: "memory");
        __syncthreads();

        float s[8][4];
        #pragma unroll
        for (int nt = 0; nt < 8; nt++) { s[nt][0]=s[nt][1]=s[nt][2]=s[nt][3]=0.f; }
        #pragma unroll
        for (int ks = 0; ks < 8; ks++) {
            const uint32_t kb = (uint32_t)ks * 32u;
            uint32_t ah[4], al_[4];
            ldsm_x4(ah,  sb + QHOFF + aRow*FROWB + aKof + kb);
            ldsm_x4(al_, sb + QLOFF + aRow*FROWB + aKof + kb);
            #pragma unroll
            for (int np = 0; np < 4; np++) {
                uint32_t bhf[4], blf[4];
                ldsm_x4(bhf, sb + KHOFF + (bRow + np*16u)*FROWB + bKof + kb);
                ldsm_x4(blf, sb + KLOFF + (bRow + np*16u)*FROWB + bKof + kb);
                mma_h(s[2*np],   ah,  bhf[0], bhf[1]);
                mma_h(s[2*np],   ah,  blf[0], blf[1]);
                mma_h(s[2*np],   al_, bhf[0], bhf[1]);
                mma_h(s[2*np+1], ah,  bhf[2], bhf[3]);
                mma_h(s[2*np+1], ah,  blf[2], blf[3]);
                mma_h(s[2*np+1], al_, bhf[2], bhf[3]);
            }
        }

        float mx0 = -1e30f, mx1 = -1e30f;
        #pragma unroll
        for (int nt = 0; nt < 8; nt++) {
            int jg = j0 + nt*8 + 2*tq;
            s[nt][0] = (jg   > ig0) ? NEGINF : s[nt][0]*rscale;
            s[nt][1] = (jg+1 > ig0) ? NEGINF : s[nt][1]*rscale;
            s[nt][2] = (jg   > ig1) ? NEGINF : s[nt][2]*rscale;
            s[nt][3] = (jg+1 > ig1) ? NEGINF : s[nt][3]*rscale;
            mx0 = fmaxf(mx0, fmaxf(s[nt][0], s[nt][1]));
            mx1 = fmaxf(mx1, fmaxf(s[nt][2], s[nt][3]));
        }
        mx0 = fmaxf(mx0, __shfl_xor_sync(0xffffffffu, mx0, 1));
        mx0 = fmaxf(mx0, __shfl_xor_sync(0xffffffffu, mx0, 2));
        mx1 = fmaxf(mx1, __shfl_xor_sync(0xffffffffu, mx1, 1));
        mx1 = fmaxf(mx1, __shfl_xor_sync(0xffffffffu, mx1, 2));
        float mn0 = fmaxf(m0r, mx0), mn1 = fmaxf(m1r, mx1);
        float co0 = __expf(m0r - mn0), co1 = __expf(m1r - mn1);
        float sum0 = 0.f, sum1 = 0.f;
        #pragma unroll
        for (int nt = 0; nt < 8; nt++) {
            s[nt][0] = __expf(s[nt][0] - mn0);
            s[nt][1] = __expf(s[nt][1] - mn0);
            s[nt][2] = __expf(s[nt][2] - mn1);
            s[nt][3] = __expf(s[nt][3] - mn1);
            sum0 += s[nt][0] + s[nt][1];
            sum1 += s[nt][2] + s[nt][3];
        }
        sum0 += __shfl_xor_sync(0xffffffffu, sum0, 1);
        sum0 += __shfl_xor_sync(0xffffffffu, sum0, 2);
        sum1 += __shfl_xor_sync(0xffffffffu, sum1, 1);
        sum1 += __shfl_xor_sync(0xffffffffu, sum1, 2);
        l0r = l0r * co0 + sum0;  m0r = mn0;
        l1r = l1r * co1 + sum1;  m1r = mn1;

        #pragma unroll
        for (int nt = 0; nt < 16; nt++) {
            o[nt][0] *= co0; o[nt][1] *= co0;
            o[nt][2] *= co1; o[nt][3] *= co1;
        }

        #pragma unroll
        for (int ks = 0; ks < 4; ks++) {
            uint32_t ph[4], pl[4];
            split_pack(s[2*ks][0],   s[2*ks][1],   ph[0], pl[0]);
            split_pack(s[2*ks][2],   s[2*ks][3],   ph[1], pl[1]);
            split_pack(s[2*ks+1][0], s[2*ks+1][1], ph[2], pl[2]);
            split_pack(s[2*ks+1][2], s[2*ks+1][3], ph[3], pl[3]);
            const uint32_t krow = (uint32_t)(ks*16) + vRow;
            #pragma unroll
            for (int np = 0; np < 8; np++) {
                uint32_t vhf[4], vlf[4];
                ldsm_x4t(vhf, sb + VHOFF + krow*FROWB + (uint32_t)(np*32) + vDof);
                ldsm_x4t(vlf, sb + VLOFF + krow*FROWB + (uint32_t)(np*32) + vDof);
                mma_h(o[2*np],   ph, vhf[0], vhf[1]);
                mma_h(o[2*np],   ph, vlf[0], vlf[1]);
                mma_h(o[2*np],   pl, vhf[0], vhf[1]);
                mma_h(o[2*np+1], ph, vhf[2], vhf[3]);
                mma_h(o[2*np+1], ph, vlf[2], vlf[3]);
                mma_h(o[2*np+1], pl, vhf[2], vhf[3]);
            }
        }
    }

    float inv0 = 1.f / l0r, inv1 = 1.f / l1r;
    float* Og = g_attn + headbase + (size_t)(q0 + w*16) * Dd;
    #pragma unroll
    for (int nt = 0; nt < 16; nt++) {
        *(float2*)&Og[(size_t)g*Dd     + nt*8 + 2*tq] = make_float2(o[nt][0]*inv0, o[nt][1]*inv0);
        *(float2*)&Og[(size_t)(g+8)*Dd + nt*8 + 2*tq] = make_float2(o[nt][2]*inv1, o[nt][3]*inv1);
    }
}

// ---------------- adapter attention ----------------
__global__ __launch_bounds__(128) void adapter_kernel(const float* __restrict__ gate)
{
    __shared__ __align__(16) float ak[ALa][HDh];
    __shared__ __align__(16) float av[ALa][HDh];
    const int t = threadIdx.x;
    const int bh = blockIdx.y;
    const int b = bh >> 5, h = bh & 31;
    const int s0 = blockIdx.x * 4;

    #pragma unroll
    for (int r = 0; r < ALa; r++) {
        int idx = t + r*128;
        int j = idx >> 7, d = idx & 127;
        ak[j][d] = g_ak[(size_t)(b*ALa + j) * Dd + h*HDh + d];
        av[j][d] = g_av[(size_t)(b*ALa + j) * Dd + h*HDh + d];
    }
    __syncthreads();

    const int w = t >> 5, lane = t & 31;
    const int s = s0 + w;
    const size_t base = (size_t)(b*Ss + s) * Dd + h*HDh;
    const float rscale = 0.08838834764831844f;

    float4 qv = *(const float4*)&g_q[base + lane*4];
    float sc[ALa];
    #pragma unroll
    for (int j = 0; j < ALa; j++) {
        float d0 = qv.x*ak[j][lane*4+0] + qv.y*ak[j][lane*4+1]
                 + qv.z*ak[j][lane*4+2] + qv.w*ak[j][lane*4+3];
        #pragma unroll
        for (int off = 16; off >= 1; off >>= 1)
            d0 += __shfl_xor_sync(0xffffffffu, d0, off);
        sc[j] = d0 * rscale;
    }
    float mx = sc[0];
    #pragma unroll
    for (int j = 1; j < ALa; j++) mx = fmaxf(mx, sc[j]);
    float sum = 0.f;
    #pragma unroll
    for (int j = 0; j < ALa; j++) { sc[j] = __expf(sc[j] - mx); sum += sc[j]; }
    float inv = 1.f / sum;
    float gg = tanhf(gate[h]);

    float acc[4] = {0.f, 0.f, 0.f, 0.f};
    #pragma unroll
    for (int j = 0; j < ALa; j++) {
        float p = sc[j] * inv;
        acc[0] += p * av[j][lane*4+0];
        acc[1] += p * av[j][lane*4+1];
        acc[2] += p * av[j][lane*4+2];
        acc[3] += p * av[j][lane*4+3];
    }
    float4 ov = *(float4*)&g_attn[base + lane*4];
    ov.x += gg*acc[0]; ov.y += gg*acc[1]; ov.z += gg*acc[2]; ov.w += gg*acc[3];
    *(float4*)&g_attn[base + lane*4] = ov;
}

// ---------------- host ----------------
extern "C" void kernel_launch(void* const* d_in, const int* in_sizes, int n_in,
                              void* d_out, int out_size)
{
    (void)in_sizes; (void)n_in; (void)out_size;
    const float* x       = (const float*)d_in[0];
    const float* cosT    = (const float*)d_in[2];
    const float* sinT    = (const float*)d_in[3];
    const float* wq      = (const float*)d_in[4];
    const float* wk      = (const float*)d_in[5];
    const float* wv      = (const float*)d_in[6];
    const float* wo      = (const float*)d_in[7];
    const float* gate    = (const float*)d_in[8];
    const float* adapter = (const float*)d_in[9];
    float* out = (float*)d_out;

    float *qp, *kp, *vp, *attnp;
    __half *ahp, *alp, *wqh, *wql, *wkh, *wkl, *wvh, *wvl, *woh, *wol;
    __half *qhp, *qlp, *khp, *klp, *vhp, *vlp;
    cudaGetSymbolAddress((void**)&qp,    g_q);
    cudaGetSymbolAddress((void**)&kp,    g_k);
    cudaGetSymbolAddress((void**)&vp,    g_v);
    cudaGetSymbolAddress((void**)&attnp, g_attn);
    cudaGetSymbolAddress((void**)&ahp,  g_ah);  cudaGetSymbolAddress((void**)&alp,  g_al);
    cudaGetSymbolAddress((void**)&wqh,  g_wqh); cudaGetSymbolAddress((void**)&wql,  g_wql);
    cudaGetSymbolAddress((void**)&wkh,  g_wkh); cudaGetSymbolAddress((void**)&wkl,  g_wkl);
    cudaGetSymbolAddress((void**)&wvh,  g_wvh); cudaGetSymbolAddress((void**)&wvl,  g_wvl);
    cudaGetSymbolAddress((void**)&woh,  g_woh); cudaGetSymbolAddress((void**)&wol,  g_wol);
    cudaGetSymbolAddress((void**)&qhp,  g_qh);  cudaGetSymbolAddress((void**)&qlp,  g_ql);
    cudaGetSymbolAddress((void**)&khp,  g_kh);  cudaGetSymbolAddress((void**)&klp,  g_kl);
    cudaGetSymbolAddress((void**)&vhp,  g_vh);  cudaGetSymbolAddress((void**)&vlp,  g_vl);

    cudaFuncSetAttribute(gemm_h3f, cudaFuncAttributeMaxDynamicSharedMemorySize, GEMM_SMEM);
    cudaFuncSetAttribute(flash_h, cudaFuncAttributeMaxDynamicSharedMemorySize, FLASH_SMEM);

    const int nXW = Mtok*Dd;
    const int cgrid = nXW/4/256;

    conv_split<<<cgrid, 256>>>(x,  ahp, alp, nXW);
    conv_split<<<cgrid, 256>>>(wq, wqh, wql, Dd*Dd);
    conv_split<<<cgrid, 256>>>(wk, wkh, wkl, Dd*Dd);
    conv_split<<<cgrid, 256>>>(wv, wvh, wvl, Dd*Dd);
    conv_split<<<cgrid, 256>>>(wo, woh, wol, Dd*Dd);

    dim3 gbig(Dd/BN, Mtok/BM);
    gemm_h3f<<<gbig, 256, GEMM_SMEM>>>(ahp, alp, wqh, wql, qp, Mtok, Dd, Dd);
    gemm_h3f<<<gbig, 256, GEMM_SMEM>>>(ahp, alp, wkh, wkl, kp, Mtok, Dd, Dd);
    gemm_h3f<<<gbig, 256, GEMM_SMEM>>>(ahp, alp, wvh, wvl, vp, Mtok, Dd, Dd);

    gemm_skinny<<<dim3(Dd/128, KSPL, 2), 128>>>(adapter, wk, wv);
    skinny_reduce<<<(20*4096 + 255)/256, 256>>>();

    int npairs = Bb*Ss*Hh*HALFh;
    rope_split<<<npairs/256, 256>>>(qp, qhp, qlp, cosT, sinT);
    rope_split<<<npairs/256, 256>>>(kp, khp, klp, cosT, sinT);
    conv_split<<<cgrid, 256>>>(vp, vhp, vlp, nXW);

    flash_h<<<dim3(Ss/FQ, Bb*Hh), 256, FLASH_SMEM>>>();
    adapter_kernel<<<dim3(Ss/4, Bb*Hh), 128>>>(gate);

    conv_split<<<cgrid, 256>>>(attnp, ahp, alp, nXW);
    gemm_h3f<<<gbig, 256, GEMM_SMEM>>>(ahp, alp, woh, wol, out, Mtok, Dd, Dd);
}